// round 6
// baseline (speedup 1.0000x reference)
#include <cuda_runtime.h>
#include <cstdint>

#define Bv   4
#define Nv   512
#define Dv   128
#define Hv   8
#define FFv  512
#define ROWS (Bv*Nv)            // 2048
#define EROWS (Bv*Nv*Nv)        // 1,048,576 rows of e
#define P1_TILE 128
#define P1_AS   132             // padded A row stride (floats): banks 4g+t, 16B aligned
#define P1_NT   8192            // EROWS / P1_TILE

// ---------------- scratch ---------------------------------------------------
__device__ float g_hn [ROWS*Dv];
__device__ float g_qkv[ROWS*3*Dv];
__device__ float g_y  [ROWS*Dv];
__device__ float g_z  [ROWS*Dv];
__device__ float g_hid[ROWS*FFv];
__device__ float g_e12[(size_t)EROWS*16];   // 64 MB: [row][h*2 + {e1,e2}]

// ---------------- helpers ---------------------------------------------------
__device__ __forceinline__ void cpa16(void* s, const void* g) {
    unsigned sa = (unsigned)__cvta_generic_to_shared(s);
    asm volatile("cp.async.cg.shared.global [%0], [%1], 16;" :: "r"(sa), "l"(g));
}
__device__ __forceinline__ void cp_commit() { asm volatile("cp.async.commit_group;"); }
__device__ __forceinline__ void cp_wait1()  { asm volatile("cp.async.wait_group 1;" ::: "memory"); }

__device__ __forceinline__ unsigned cvt_tf32(float x) {
    unsigned u; asm("cvt.rna.tf32.f32 %0, %1;" : "=r"(u) : "f"(x)); return u;
}
__device__ __forceinline__ void mma_tf32(float c[4], const unsigned a[4],
                                         unsigned b0, unsigned b1) {
    asm volatile("mma.sync.aligned.m16n8k8.row.col.f32.tf32.tf32.f32 "
                 "{%0,%1,%2,%3},{%4,%5,%6,%7},{%8,%9},{%0,%1,%2,%3};"
                 : "+f"(c[0]), "+f"(c[1]), "+f"(c[2]), "+f"(c[3])
                 : "r"(a[0]), "r"(a[1]), "r"(a[2]), "r"(a[3]), "r"(b0), "r"(b1));
}

// ---------------- rmsnorm: warp per row -------------------------------------
__global__ void rmsnorm_k(const float* __restrict__ x, const float* __restrict__ add,
                          const float* __restrict__ w, float* __restrict__ out) {
    int row  = blockIdx.x * 8 + (threadIdx.x >> 5);
    int lane = threadIdx.x & 31;
    float4 v = ((const float4*)(x + (size_t)row*Dv))[lane];
    if (add) {
        float4 a = ((const float4*)(add + (size_t)row*Dv))[lane];
        v.x += a.x; v.y += a.y; v.z += a.z; v.w += a.w;
    }
    float ss = v.x*v.x + v.y*v.y + v.z*v.z + v.w*v.w;
    #pragma unroll
    for (int off = 16; off; off >>= 1) ss += __shfl_xor_sync(0xffffffffu, ss, off);
    float s = rsqrtf(ss * (1.0f/Dv) + 1e-5f);
    float4 wv = ((const float4*)w)[lane];
    ((float4*)(out + (size_t)row*Dv))[lane] =
        make_float4(v.x*s*wv.x, v.y*s*wv.y, v.z*s*wv.z, v.w*s*wv.w);
}

// ---------------- tiled GEMM 64x64, BK=32, 256 threads ----------------------
template<bool GELU, bool ADDC>
__global__ void gemm64(const float* __restrict__ A, const float* __restrict__ B,
                       const float* __restrict__ Cadd, float* __restrict__ C,
                       int M, int Nn, int K) {
    __shared__ float Ast[32*64];
    __shared__ float Bs [32*64];
    int tid = threadIdx.x;
    int bm = blockIdx.y, bn = blockIdx.x;
    int tx = tid & 15, ty = tid >> 4;
    float acc[4][4] = {};
    for (int k0 = 0; k0 < K; k0 += 32) {
        for (int u = tid; u < 512; u += 256) {
            int r = u >> 3, c4 = u & 7;
            float4 a = *(const float4*)&A[(size_t)(bm*64 + r)*K + k0 + c4*4];
            Ast[(c4*4+0)*64 + r] = a.x; Ast[(c4*4+1)*64 + r] = a.y;
            Ast[(c4*4+2)*64 + r] = a.z; Ast[(c4*4+3)*64 + r] = a.w;
        }
        for (int u = tid; u < 512; u += 256) {
            int kk = u >> 4, n4 = u & 15;
            *(float4*)&Bs[kk*64 + n4*4] =
                *(const float4*)&B[(size_t)(k0+kk)*Nn + bn*64 + n4*4];
        }
        __syncthreads();
        #pragma unroll
        for (int kk = 0; kk < 32; kk++) {
            float4 a4 = *(const float4*)&Ast[kk*64 + ty*4];
            float4 b4 = *(const float4*)&Bs [kk*64 + tx*4];
            float av[4] = {a4.x, a4.y, a4.z, a4.w};
            float bv[4] = {b4.x, b4.y, b4.z, b4.w};
            #pragma unroll
            for (int i = 0; i < 4; i++)
                #pragma unroll
                for (int j = 0; j < 4; j++)
                    acc[i][j] = fmaf(av[i], bv[j], acc[i][j]);
        }
        __syncthreads();
    }
    #pragma unroll
    for (int i = 0; i < 4; i++) {
        int r = bm*64 + ty*4 + i;
        #pragma unroll
        for (int j = 0; j < 4; j++) {
            int c = bn*64 + tx*4 + j;
            float v = acc[i][j];
            if (GELU) v = 0.5f * v * (1.0f + erff(v * 0.70710678118654752f));
            if (ADDC) v += Cadd[(size_t)r*Nn + c];
            C[(size_t)r*Nn + c] = v;
        }
    }
}

// ---------------- PASS 1: e12 = e @ W_e (tf32 mma, 3-term hi/lo) -----------
// Output column order n: e12[row][n] with n = h*2 + which  (which: 0=e1, 1=e2)
// so We column for logical n is  (n&1)*Hv + (n>>1).
#define P1_SMEM ((2*P1_TILE*P1_AS + 16*2*2*32)*4)

__global__ void __launch_bounds__(256, 1) eproj_k(
    const float* __restrict__ e, const float* __restrict__ We,
    float* __restrict__ e12)
{
    extern __shared__ float sm[];
    float* As  = sm;                          // 2 * 128*132
    float* blo = sm + 2*P1_TILE*P1_AS;        // [16][2][2][32]

    const int tid  = threadIdx.x;
    const int warp = tid >> 5, lane = tid & 31;
    const int g = lane >> 2, t = lane & 3;

    // B fragments: hi in regs, lo in smem (per-lane layout, conflict-free)
    unsigned bhi[16][2][2];
    #pragma unroll
    for (int kk = 0; kk < 16; kk++)
        #pragma unroll
        for (int nt = 0; nt < 2; nt++)
            #pragma unroll
            for (int r = 0; r < 2; r++) {
                int k = kk*8 + t + r*4;
                int n = nt*8 + g;                       // logical output col
                int wcol = (n & 1)*Hv + (n >> 1);       // permuted We column
                float w = We[k*16 + wcol];
                unsigned hi = cvt_tf32(w);
                bhi[kk][nt][r] = hi;
                if (warp == 0) {
                    unsigned lo = cvt_tf32(w - __uint_as_float(hi));
                    blo[((kk*2 + nt)*2 + r)*32 + lane] = __uint_as_float(lo);
                }
            }
    __syncthreads();

    auto load_tile = [&](int tile, int par) {
        const float4* src = (const float4*)(e + (size_t)tile*P1_TILE*Dv);
        float* dst = As + par*P1_TILE*P1_AS;
        #pragma unroll
        for (int u = tid; u < P1_TILE*32; u += 256) {
            int r = u >> 5, c4 = u & 31;
            cpa16(dst + r*P1_AS + c4*4, src + (size_t)r*32 + c4);
        }
    };

    int tile = blockIdx.x;
    const int stride = gridDim.x;
    if (tile < P1_NT) load_tile(tile, 0);
    cp_commit();
    int par = 0;
    for (; tile < P1_NT; tile += stride) {
        int nxt = tile + stride;
        if (nxt < P1_NT) load_tile(nxt, par ^ 1);
        cp_commit();
        cp_wait1();
        __syncthreads();

        float c[2][4] = {};
        const float* A = As + par*P1_TILE*P1_AS + warp*16*P1_AS;
        #pragma unroll
        for (int kk = 0; kk < 16; kk++) {
            float a0f = A[ g     *P1_AS + kk*8 + t    ];
            float a1f = A[(g + 8)*P1_AS + kk*8 + t    ];
            float a2f = A[ g     *P1_AS + kk*8 + t + 4];
            float a3f = A[(g + 8)*P1_AS + kk*8 + t + 4];
            unsigned ah[4] = {cvt_tf32(a0f), cvt_tf32(a1f), cvt_tf32(a2f), cvt_tf32(a3f)};
            unsigned al[4] = {
                cvt_tf32(a0f - __uint_as_float(ah[0])),
                cvt_tf32(a1f - __uint_as_float(ah[1])),
                cvt_tf32(a2f - __uint_as_float(ah[2])),
                cvt_tf32(a3f - __uint_as_float(ah[3]))};
            #pragma unroll
            for (int nt = 0; nt < 2; nt++) {
                unsigned bl0 = __float_as_uint(blo[((kk*2 + nt)*2 + 0)*32 + lane]);
                unsigned bl1 = __float_as_uint(blo[((kk*2 + nt)*2 + 1)*32 + lane]);
                mma_tf32(c[nt], ah, bhi[kk][nt][0], bhi[kk][nt][1]); // hi*hi
                mma_tf32(c[nt], al, bhi[kk][nt][0], bhi[kk][nt][1]); // lo*hi
                mma_tf32(c[nt], ah, bl0, bl1);                      // hi*lo
            }
        }
        float* out = e12 + ((size_t)tile*P1_TILE + warp*16)*16;
        #pragma unroll
        for (int nt = 0; nt < 2; nt++) {
            *(float2*)&out[ g     *16 + nt*8 + 2*t] = make_float2(c[nt][0], c[nt][1]);
            *(float2*)&out[(g + 8)*16 + nt*8 + 2*t] = make_float2(c[nt][2], c[nt][3]);
        }
        __syncthreads();
        par ^= 1;
    }
}

// ---------------- PASS 2: streaming attention (online softmax, no max) -----
// grid: 256 blocks (b, 8 i-rows). 256 threads: tid -> (i local, h, c-quad s).
__global__ void __launch_bounds__(256) attn2_k(
    const float* __restrict__ qkv, const float* __restrict__ e12,
    float* __restrict__ yout)
{
    const int tid = threadIdx.x;
    const int b  = blockIdx.x >> 6;
    const int i  = (blockIdx.x & 63)*8 + (tid >> 5);
    const int h  = (tid >> 2) & 7;
    const int s  = tid & 3;

    float4 q = *(const float4*)(qkv + ((size_t)(b*Nv + i)*384) + h*16 + s*4);
    q.x *= 0.25f; q.y *= 0.25f; q.z *= 0.25f; q.w *= 0.25f;

    const float* kbase = qkv + (size_t)b*Nv*384 + 128 + h*16 + s*4;
    const float* vbase = kbase + 128;
    const float* ebase = e12 + (size_t)(b*Nv + i)*Nv*16 + h*2;

    float4 acc = make_float4(0.f, 0.f, 0.f, 0.f);
    float sden = 0.f;
    #pragma unroll 4
    for (int j = 0; j < Nv; j++) {
        float4 kv = *(const float4*)(kbase + (size_t)j*384);
        float part = q.x*kv.x;
        part = fmaf(q.y, kv.y, part);
        part = fmaf(q.z, kv.z, part);
        part = fmaf(q.w, kv.w, part);
        part += __shfl_xor_sync(0xffffffffu, part, 1);
        part += __shfl_xor_sync(0xffffffffu, part, 2);
        float2 ee = *(const float2*)(ebase + (size_t)j*16);
        float p  = __expf(part + ee.x);
        float pe = p * ee.y;
        sden += p;
        float4 vv = *(const float4*)(vbase + (size_t)j*384);
        acc.x = fmaf(pe, vv.x, acc.x);
        acc.y = fmaf(pe, vv.y, acc.y);
        acc.z = fmaf(pe, vv.z, acc.z);
        acc.w = fmaf(pe, vv.w, acc.w);
    }
    float inv = 1.0f / sden;
    ((float4*)(yout + (size_t)(b*Nv + i)*Dv))[h*4 + s] =
        make_float4(acc.x*inv, acc.y*inv, acc.z*inv, acc.w*inv);
}

// ---------------- host launch ----------------------------------------------
extern "C" void kernel_launch(void* const* d_in, const int* in_sizes, int n_in,
                              void* d_out, int out_size) {
    const float* h    = (const float*)d_in[0];
    const float* e    = (const float*)d_in[1];
    const float* W_h  = (const float*)d_in[2];
    const float* W_e  = (const float*)d_in[3];
    const float* n1   = (const float*)d_in[4];
    const float* n2   = (const float*)d_in[5];
    const float* W_fc = (const float*)d_in[6];
    const float* W_pr = (const float*)d_in[7];
    float* out = (float*)d_out;

    float *p_hn, *p_qkv, *p_y, *p_z, *p_hid, *p_e12;
    cudaGetSymbolAddress((void**)&p_hn,  g_hn);
    cudaGetSymbolAddress((void**)&p_qkv, g_qkv);
    cudaGetSymbolAddress((void**)&p_y,   g_y);
    cudaGetSymbolAddress((void**)&p_z,   g_z);
    cudaGetSymbolAddress((void**)&p_hid, g_hid);
    cudaGetSymbolAddress((void**)&p_e12, g_e12);

    cudaFuncSetAttribute(eproj_k, cudaFuncAttributeMaxDynamicSharedMemorySize, P1_SMEM);

    // 1) hn = rmsnorm(h)
    rmsnorm_k<<<ROWS/8, 256>>>(h, nullptr, n1, p_hn);
    // 2) qkv = hn @ W_h
    gemm64<false,false><<<dim3(384/64, ROWS/64), 256>>>(p_hn, W_h, nullptr, p_qkv,
                                                        ROWS, 3*Dv, Dv);
    // 3a) e12 = e @ W_e (tf32 mma, streaming)
    eproj_k<<<148, 256, P1_SMEM>>>(e, W_e, p_e12);
    // 3b) attention with precomputed e1/e2 -> y
    attn2_k<<<Bv*(Nv/8), 256>>>(p_qkv, p_e12, p_y);
    // 4) z = rmsnorm(y + h)
    rmsnorm_k<<<ROWS/8, 256>>>(p_y, h, n2, p_z);
    // 5) hid = gelu(z @ W_fc)
    gemm64<true,false><<<dim3(FFv/64, ROWS/64), 256>>>(p_z, W_fc, nullptr, p_hid,
                                                       ROWS, FFv, Dv);
    // 6) out = hid @ W_proj + y
    gemm64<false,true><<<dim3(Dv/64, ROWS/64), 256>>>(p_hid, W_pr, p_y, out,
                                                      ROWS, Dv, FFv);
}

// round 7
// speedup vs baseline: 1.9227x; 1.9227x over previous
#include <cuda_runtime.h>
#include <cstdint>

#define Bv   4
#define Nv   512
#define Dv   128
#define Hv   8
#define FFv  512
#define ROWS (Bv*Nv)
#define P1_NT 8192              // e tiles of 128 rows

__device__ float g_hn [ROWS*Dv];
__device__ float g_qkv[ROWS*3*Dv];
__device__ float g_y  [ROWS*Dv];
__device__ float g_z  [ROWS*Dv];
__device__ float g_hid[ROWS*FFv];
__device__ float g_e12[(size_t)ROWS*Nv*16];   // 64 MB [b,i,j][h*2+{e1,e2}]

__device__ __forceinline__ void cpa16(void* s, const void* g) {
    unsigned sa = (unsigned)__cvta_generic_to_shared(s);
    asm volatile("cp.async.cg.shared.global [%0], [%1], 16;" :: "r"(sa), "l"(g));
}
__device__ __forceinline__ void cp_commit() { asm volatile("cp.async.commit_group;"); }
__device__ __forceinline__ void cp_wait1()  { asm volatile("cp.async.wait_group 1;" ::: "memory"); }
__device__ __forceinline__ unsigned cvt_tf32(float x) {
    unsigned u; asm("cvt.rna.tf32.f32 %0, %1;" : "=r"(u) : "f"(x)); return u;
}
__device__ __forceinline__ void mma_tf32(float c[4], const unsigned a[4],
                                         unsigned b0, unsigned b1) {
    asm volatile("mma.sync.aligned.m16n8k8.row.col.f32.tf32.tf32.f32 "
                 "{%0,%1,%2,%3},{%4,%5,%6,%7},{%8,%9},{%0,%1,%2,%3};"
                 : "+f"(c[0]), "+f"(c[1]), "+f"(c[2]), "+f"(c[3])
                 : "r"(a[0]), "r"(a[1]), "r"(a[2]), "r"(a[3]), "r"(b0), "r"(b1));
}

// ---------------- rmsnorm ---------------------------------------------------
__global__ void rmsnorm_k(const float* __restrict__ x, const float* __restrict__ add,
                          const float* __restrict__ w, float* __restrict__ out) {
    int row  = blockIdx.x * 8 + (threadIdx.x >> 5);
    int lane = threadIdx.x & 31;
    float4 v = ((const float4*)(x + (size_t)row*Dv))[lane];
    if (add) {
        float4 a = ((const float4*)(add + (size_t)row*Dv))[lane];
        v.x += a.x; v.y += a.y; v.z += a.z; v.w += a.w;
    }
    float ss = v.x*v.x + v.y*v.y + v.z*v.z + v.w*v.w;
    #pragma unroll
    for (int off = 16; off; off >>= 1) ss += __shfl_xor_sync(0xffffffffu, ss, off);
    float s = rsqrtf(ss * (1.0f/Dv) + 1e-5f);
    float4 wv = ((const float4*)w)[lane];
    ((float4*)(out + (size_t)row*Dv))[lane] =
        make_float4(v.x*s*wv.x, v.y*s*wv.y, v.z*s*wv.z, v.w*s*wv.w);
}

// ---------------- tiled GEMM 64x64 ------------------------------------------
template<bool GELU, bool ADDC>
__global__ void gemm64(const float* __restrict__ A, const float* __restrict__ B,
                       const float* __restrict__ Cadd, float* __restrict__ C,
                       int M, int Nn, int K) {
    __shared__ float Ast[32*64];
    __shared__ float Bs [32*64];
    int tid = threadIdx.x;
    int bm = blockIdx.y, bn = blockIdx.x;
    int tx = tid & 15, ty = tid >> 4;
    float acc[4][4] = {};
    for (int k0 = 0; k0 < K; k0 += 32) {
        for (int u = tid; u < 512; u += 256) {
            int r = u >> 3, c4 = u & 7;
            float4 a = *(const float4*)&A[(size_t)(bm*64 + r)*K + k0 + c4*4];
            Ast[(c4*4+0)*64 + r] = a.x; Ast[(c4*4+1)*64 + r] = a.y;
            Ast[(c4*4+2)*64 + r] = a.z; Ast[(c4*4+3)*64 + r] = a.w;
        }
        for (int u = tid; u < 512; u += 256) {
            int kk = u >> 4, n4 = u & 15;
            *(float4*)&Bs[kk*64 + n4*4] =
                *(const float4*)&B[(size_t)(k0+kk)*Nn + bn*64 + n4*4];
        }
        __syncthreads();
        #pragma unroll
        for (int kk = 0; kk < 32; kk++) {
            float4 a4 = *(const float4*)&Ast[kk*64 + ty*4];
            float4 b4 = *(const float4*)&Bs [kk*64 + tx*4];
            float av[4] = {a4.x, a4.y, a4.z, a4.w};
            float bv[4] = {b4.x, b4.y, b4.z, b4.w};
            #pragma unroll
            for (int i = 0; i < 4; i++)
                #pragma unroll
                for (int j = 0; j < 4; j++)
                    acc[i][j] = fmaf(av[i], bv[j], acc[i][j]);
        }
        __syncthreads();
    }
    #pragma unroll
    for (int i = 0; i < 4; i++) {
        int r = bm*64 + ty*4 + i;
        #pragma unroll
        for (int j = 0; j < 4; j++) {
            int c = bn*64 + tx*4 + j;
            float v = acc[i][j];
            if (GELU) v = 0.5f * v * (1.0f + erff(v * 0.70710678118654752f));
            if (ADDC) v += Cadd[(size_t)r*Nn + c];
            C[(size_t)r*Nn + c] = v;
        }
    }
}

// ---------------- PASS 1: e12 = e @ W_e (tf32 mma, A direct from LDG) -------
// k permutation per mma step kk=(kkp,s): frag-k t -> col kkp*16+4t+2s,
// frag-k t+4 -> +1.  Lane's A frag = its own contiguous 16B (two LDG.128/row-pair).
__global__ void __launch_bounds__(256) eproj2_k(
    const float* __restrict__ e, const float* __restrict__ We,
    float* __restrict__ e12)
{
    __shared__ float2 sbhi[16*2*32];
    __shared__ float2 sblo[16*2*32];
    const int tid = threadIdx.x;
    const int warp = tid >> 5, lane = tid & 31;
    const int g = lane >> 2, t = lane & 3;

    if (warp == 0) {
        #pragma unroll
        for (int kk = 0; kk < 16; kk++) {
            int kkp = kk >> 1, s = kk & 1;
            int c0 = kkp*16 + 4*t + 2*s;
            #pragma unroll
            for (int nt = 0; nt < 2; nt++) {
                int n = nt*8 + g;
                int wcol = (n & 1)*Hv + (n >> 1);
                float w0 = We[c0*16 + wcol], w1 = We[(c0+1)*16 + wcol];
                unsigned h0 = cvt_tf32(w0), h1 = cvt_tf32(w1);
                sbhi[(kk*2+nt)*32 + lane] =
                    make_float2(__uint_as_float(h0), __uint_as_float(h1));
                sblo[(kk*2+nt)*32 + lane] = make_float2(
                    __uint_as_float(cvt_tf32(w0 - __uint_as_float(h0))),
                    __uint_as_float(cvt_tf32(w1 - __uint_as_float(h1))));
            }
        }
    }
    __syncthreads();

    for (int tile = blockIdx.x; tile < P1_NT; tile += gridDim.x) {
        const float4* A = (const float4*)(e + ((size_t)tile*128 + warp*16)*Dv);
        float c[2][4] = {};
        #pragma unroll
        for (int kkp = 0; kkp < 8; kkp++) {
            float4 alo = A[(size_t) g    *32 + kkp*4 + t];
            float4 ahi = A[(size_t)(g+8)*32 + kkp*4 + t];
            #pragma unroll
            for (int s = 0; s < 2; s++) {
                int kk = kkp*2 + s;
                float a0f = s ? alo.z : alo.x;   // row g,   k=t
                float a1f = s ? ahi.z : ahi.x;   // row g+8, k=t
                float a2f = s ? alo.w : alo.y;   // row g,   k=t+4
                float a3f = s ? ahi.w : ahi.y;   // row g+8, k=t+4
                unsigned ah[4] = {cvt_tf32(a0f), cvt_tf32(a1f),
                                  cvt_tf32(a2f), cvt_tf32(a3f)};
                unsigned al[4] = {
                    cvt_tf32(a0f - __uint_as_float(ah[0])),
                    cvt_tf32(a1f - __uint_as_float(ah[1])),
                    cvt_tf32(a2f - __uint_as_float(ah[2])),
                    cvt_tf32(a3f - __uint_as_float(ah[3]))};
                #pragma unroll
                for (int nt = 0; nt < 2; nt++) {
                    float2 bh = sbhi[(kk*2+nt)*32 + lane];
                    float2 bl = sblo[(kk*2+nt)*32 + lane];
                    unsigned b0 = __float_as_uint(bh.x), b1 = __float_as_uint(bh.y);
                    mma_tf32(c[nt], ah, b0, b1);
                    mma_tf32(c[nt], al, b0, b1);
                    mma_tf32(c[nt], ah, __float_as_uint(bl.x), __float_as_uint(bl.y));
                }
            }
        }
        float* out = e12 + ((size_t)tile*128 + warp*16)*16;
        #pragma unroll
        for (int nt = 0; nt < 2; nt++) {
            *(float2*)&out[ g    *16 + nt*8 + 2*t] = make_float2(c[nt][0], c[nt][1]);
            *(float2*)&out[(g+8)*16 + nt*8 + 2*t] = make_float2(c[nt][2], c[nt][3]);
        }
    }
}

// ---------------- PASS 2: tiled attention -----------------------------------
// block = (b, 16 i), 512 threads: i=tid>>5, h=(tid>>2)&7, s=tid&3.
// k/v j-tiles (32x128 f) double-buffered in smem; e12 streamed via LDG.
#define ATTN_SMEM (4*32*128*4)   // 2 bufs x (k+v) x 16KB = 64KB

__global__ void __launch_bounds__(512, 1) attn3_k(
    const float* __restrict__ qkv, const float* __restrict__ e12,
    float* __restrict__ yout)
{
    extern __shared__ float sm[];
    float* ks = sm;               // [2][32][128]
    float* vs = sm + 2*32*128;

    const int tid = threadIdx.x;
    const int b  = blockIdx.x >> 5;
    const int i0 = (blockIdx.x & 31) * 16;
    const int i  = tid >> 5, hh = (tid >> 2) & 7, s = tid & 3;

    float4 q = *(const float4*)(qkv + (size_t)(b*Nv + i0 + i)*384 + hh*16 + s*4);
    q.x *= 0.25f; q.y *= 0.25f; q.z *= 0.25f; q.w *= 0.25f;

    const float* ebase = e12 + ((size_t)(b*Nv + i0 + i)*Nv)*16 + hh*2;

    auto load_tile = [&](int jt, int par) {
        #pragma unroll
        for (int ph = 0; ph < 2; ph++) {
            int u  = tid + ph*512;               // 1024 slots: j=u>>5, x4=u&31
            int j  = u >> 5, x4 = u & 31;
            const float* src = qkv + (size_t)(b*Nv + jt*32 + j)*384 + 128 + x4*4;
            cpa16(ks + par*4096 + j*128 + x4*4, src);
            cpa16(vs + par*4096 + j*128 + x4*4, src + 128);
        }
    };

    float4 acc = make_float4(0.f,0.f,0.f,0.f);
    float den = 0.f;

    load_tile(0, 0);
    cp_commit();
    for (int jt = 0; jt < 16; jt++) {
        int par = jt & 1;
        if (jt + 1 < 16) load_tile(jt + 1, par ^ 1);
        cp_commit();
        cp_wait1();
        __syncthreads();

        const float* kt = ks + par*4096;
        const float* vt = vs + par*4096;
        const float* eb = ebase + (size_t)jt*32*16;
        #pragma unroll 8
        for (int jj = 0; jj < 32; jj++) {
            float4 kv = *(const float4*)(kt + jj*128 + hh*16 + s*4);
            float d = q.x*kv.x;
            d = fmaf(q.y, kv.y, d);
            d = fmaf(q.z, kv.z, d);
            d = fmaf(q.w, kv.w, d);
            d += __shfl_xor_sync(0xffffffffu, d, 1);
            d += __shfl_xor_sync(0xffffffffu, d, 2);
            float2 ee = *(const float2*)(eb + jj*16);
            float p  = __expf(d + ee.x);
            den += p;
            float pe = p * ee.y;
            float4 vv = *(const float4*)(vt + jj*128 + hh*16 + s*4);
            acc.x = fmaf(pe, vv.x, acc.x);
            acc.y = fmaf(pe, vv.y, acc.y);
            acc.z = fmaf(pe, vv.z, acc.z);
            acc.w = fmaf(pe, vv.w, acc.w);
        }
        __syncthreads();
    }
    float inv = 1.0f / den;
    ((float4*)(yout + (size_t)(b*Nv + i0 + i)*Dv))[hh*4 + s] =
        make_float4(acc.x*inv, acc.y*inv, acc.z*inv, acc.w*inv);
}

// ---------------- host launch ----------------------------------------------
extern "C" void kernel_launch(void* const* d_in, const int* in_sizes, int n_in,
                              void* d_out, int out_size) {
    const float* h    = (const float*)d_in[0];
    const float* e    = (const float*)d_in[1];
    const float* W_h  = (const float*)d_in[2];
    const float* W_e  = (const float*)d_in[3];
    const float* n1   = (const float*)d_in[4];
    const float* n2   = (const float*)d_in[5];
    const float* W_fc = (const float*)d_in[6];
    const float* W_pr = (const float*)d_in[7];
    float* out = (float*)d_out;

    float *p_hn, *p_qkv, *p_y, *p_z, *p_hid, *p_e12;
    cudaGetSymbolAddress((void**)&p_hn,  g_hn);
    cudaGetSymbolAddress((void**)&p_qkv, g_qkv);
    cudaGetSymbolAddress((void**)&p_y,   g_y);
    cudaGetSymbolAddress((void**)&p_z,   g_z);
    cudaGetSymbolAddress((void**)&p_hid, g_hid);
    cudaGetSymbolAddress((void**)&p_e12, g_e12);

    cudaFuncSetAttribute(attn3_k, cudaFuncAttributeMaxDynamicSharedMemorySize,
                         ATTN_SMEM);

    rmsnorm_k<<<ROWS/8, 256>>>(h, nullptr, n1, p_hn);
    gemm64<false,false><<<dim3(384/64, ROWS/64), 256>>>(p_hn, W_h, nullptr, p_qkv,
                                                        ROWS, 3*Dv, Dv);
    eproj2_k<<<592, 256>>>(e, W_e, p_e12);
    attn3_k<<<Bv*(Nv/16), 512, ATTN_SMEM>>>(p_qkv, p_e12, p_y);
    rmsnorm_k<<<ROWS/8, 256>>>(p_y, h, n2, p_z);
    gemm64<true,false><<<dim3(FFv/64, ROWS/64), 256>>>(p_z, W_fc, nullptr, p_hid,
                                                       ROWS, FFv, Dv);
    gemm64<false,true><<<dim3(Dv/64, ROWS/64), 256>>>(p_hid, W_pr, p_y, out,
                                                      ROWS, Dv, FFv);
}